// round 8
// baseline (speedup 1.0000x reference)
#include <cuda_runtime.h>
#include <cstdint>

#define NT     256
#define ETILE  64
#define HID    128
#define SROW   512                      // bytes per edge-row, 32 chunks of 16B, XOR-swizzled
#define ZBUF   (ETILE * SROW)           // 32768 B per buffer
#define OFF_PRT 0                       // 64 edges * 4 cgroups * 4B = 1024
#define OFF_Z   1024
#define SMEM_BYTES (OFF_Z + 2 * ZBUF)   // 66560 B -> 1 CTA/SM

#define NS_U 6400000                    // student table in uint32 (fp16 pairs)
#define NC_U 1280000
__device__ uint32_t g_zh[NS_U + NC_U];  // fp16 tables scratch (31 MB)

// ---------------- helpers ----------------
__device__ __forceinline__ uint32_t smem_u32(const void* p) {
    uint32_t a;
    asm("{ .reg .u64 t; cvta.to.shared.u64 t, %1; cvt.u32.u64 %0, t; }" : "=r"(a) : "l"(p));
    return a;
}
__device__ __forceinline__ uint32_t hfpair(float lo, float hi) {
    uint32_t r;
    asm("cvt.rn.f16x2.f32 %0, %1, %2;" : "=r"(r) : "f"(hi), "f"(lo));
    return r;
}
__device__ __forceinline__ void ldmat4(uint32_t (&r)[4], uint32_t addr) {
    asm volatile("ldmatrix.sync.aligned.m8n8.x4.shared.b16 {%0,%1,%2,%3}, [%4];"
                 : "=r"(r[0]), "=r"(r[1]), "=r"(r[2]), "=r"(r[3]) : "r"(addr));
}
__device__ __forceinline__ void mma16816(float (&d)[4], const uint32_t (&a)[4],
                                         uint32_t b0, uint32_t b1) {
    asm volatile("mma.sync.aligned.m16n8k16.row.col.f32.f16.f16.f32 "
                 "{%0,%1,%2,%3}, {%4,%5,%6,%7}, {%8,%9}, {%0,%1,%2,%3};"
                 : "+f"(d[0]), "+f"(d[1]), "+f"(d[2]), "+f"(d[3])
                 : "r"(a[0]), "r"(a[1]), "r"(a[2]), "r"(a[3]), "r"(b0), "r"(b1));
}
#define CP_ASYNC16(dst, src) \
    asm volatile("cp.async.cg.shared.global [%0], [%1], 16;" :: "r"(dst), "l"(src) : "memory")
#define CP_COMMIT() asm volatile("cp.async.commit_group;" ::: "memory")
#define CP_WAIT(n)  asm volatile("cp.async.wait_group %0;" :: "n"(n) : "memory")

// ---------------- table convert: fp32 -> fp16 pairs (run each call) ----------------
__global__ void cvt_tables(const float* __restrict__ zs, const float* __restrict__ zc) {
    const int total = NS_U + NC_U;
    for (int i = blockIdx.x * blockDim.x + threadIdx.x; i < total;
         i += gridDim.x * blockDim.x) {
        const float* src = (i < NS_U) ? (zs + 2 * (size_t)i)
                                      : (zc + 2 * (size_t)(i - NS_U));
        g_zh[i] = hfpair(src[0], src[1]);
    }
}

// ---------------- gather via cp.async: 8 threads/edge, 2 passes of 32 edges ----------------
// q = tid&7 covers consecutive 16B chunks -> coalesced 128B lines.
__device__ __forceinline__ void gather_async(const int* __restrict__ row,
                                             const int* __restrict__ col,
                                             int base, int E, int tid, uint32_t zdst) {
    const int q = tid & 7;
    #pragma unroll
    for (int pass = 0; pass < 2; pass++) {
        const int e_t = (tid >> 3) + pass * 32;
        const int eg  = base + e_t;
        const int ri  = (eg < E) ? row[eg] : 0;
        const int ci  = (eg < E) ? col[eg] : 0;
        const char* su = (const char*)(g_zh + (size_t)ri * 64);
        const char* cu = (const char*)(g_zh + NS_U + (size_t)ci * 64);
        const uint32_t rowp = zdst + (uint32_t)e_t * SROW;
        #pragma unroll
        for (int j = 0; j < 4; j++) {
            const int c  = 8 * j + q;                   // chunk index 0..31
            const int cs = (c & 24) | ((c ^ e_t) & 7);  // XOR swizzle
            const char* src = (j < 2) ? (su + (c & 15) * 16) : (cu + (c & 15) * 16);
            CP_ASYNC16(rowp + cs * 16, src);
        }
    }
}

// ---------------- kernel ----------------
__global__ void __launch_bounds__(NT, 1)
edge_decoder_mma(const int* __restrict__ row, const int* __restrict__ col,
                 const float* __restrict__ W1, const float* __restrict__ b1,
                 const float* __restrict__ W2, const float* __restrict__ b2,
                 float* __restrict__ out, int E)
{
    extern __shared__ __align__(16) char sm[];
    float* prt = (float*)(sm + OFF_PRT);   // [64 edges][4 cgroups]
    char*  zsm = sm + OFF_Z;

    const int tid  = threadIdx.x;
    const int lane = tid & 31;
    const int wid  = tid >> 5;    // 0..7
    const int egrp = wid >> 2;    // 0..1: 32-edge slice
    const int cgrp = wid & 3;     // 0..3: 32-col slice
    const int tq   = lane & 3;
    const int tr   = lane >> 2;
    const int wcol = cgrp * 32;

    // ---- B = W1 fragments, fp16, register-resident (128 regs) ----
    uint32_t B[4][16][2];
    #pragma unroll
    for (int nb = 0; nb < 4; nb++) {
        const int n = wcol + nb * 8 + tr;
        #pragma unroll
        for (int s = 0; s < 16; s++) {
            #pragma unroll
            for (int hh = 0; hh < 2; hh++) {
                const int k0 = s * 16 + tq * 2 + hh * 8;
                B[nb][s][hh] = hfpair(W1[(size_t)k0 * HID + n],
                                      W1[(size_t)(k0 + 1) * HID + n]);
            }
        }
    }

    // ---- epilogue constants ----
    float b1v[4][2], w2v[4][2];
    #pragma unroll
    for (int nb = 0; nb < 4; nb++)
        #pragma unroll
        for (int j = 0; j < 2; j++) {
            int c = wcol + nb * 8 + tq * 2 + j;
            b1v[nb][j] = b1[c];
            w2v[nb][j] = W2[c];
        }
    const float b2v = b2[0];

    const uint32_t zb0 = smem_u32(zsm);
    const int r0  = lane & 15;
    const int hh0 = lane >> 4;

    const int numTiles = (E + ETILE - 1) / ETILE;
    int t = blockIdx.x;
    int buf = 0;

    if (t < numTiles) {
        gather_async(row, col, t * ETILE, E, tid, zb0);
        CP_COMMIT();
    }

    while (t < numTiles) {
        const int tn = t + gridDim.x;

        // issue next tile's gather into other buffer, then wait for current
        if (tn < numTiles) {
            gather_async(row, col, tn * ETILE, E, tid, zb0 + (uint32_t)(buf ^ 1) * ZBUF);
            CP_COMMIT();
            CP_WAIT(1);
        } else {
            CP_WAIT(0);
        }
        __syncthreads();   // buf visible to all; prt from prev tile consumed

        // ---- MMA mainloop ----
        float D[2][4][4];
        #pragma unroll
        for (int mb = 0; mb < 2; mb++)
            #pragma unroll
            for (int nb = 0; nb < 4; nb++)
                #pragma unroll
                for (int i = 0; i < 4; i++) D[mb][nb][i] = 0.f;

        const uint32_t zb = zb0 + (uint32_t)buf * ZBUF;
        #pragma unroll
        for (int s = 0; s < 16; s++) {
            uint32_t A[2][4];
            #pragma unroll
            for (int mb = 0; mb < 2; mb++) {
                const int r  = egrp * 32 + mb * 16 + r0;
                const int c  = 2 * s + hh0;
                const int cs = (c & 24) | ((c ^ r) & 7);
                ldmat4(A[mb], zb + (uint32_t)(r * SROW + cs * 16));
            }
            #pragma unroll
            for (int mb = 0; mb < 2; mb++)
                #pragma unroll
                for (int nb = 0; nb < 4; nb++)
                    mma16816(D[mb][nb], A[mb], B[nb][s][0], B[nb][s][1]);
        }

        // ---- epilogue: bias + ReLU + W2, quad-reduce, stash partials ----
        #pragma unroll
        for (int mb = 0; mb < 2; mb++) {
            float s0 = 0.f, s1 = 0.f;
            #pragma unroll
            for (int nb = 0; nb < 4; nb++) {
                s0 += fmaxf(D[mb][nb][0] + b1v[nb][0], 0.f) * w2v[nb][0];
                s0 += fmaxf(D[mb][nb][1] + b1v[nb][1], 0.f) * w2v[nb][1];
                s1 += fmaxf(D[mb][nb][2] + b1v[nb][0], 0.f) * w2v[nb][0];
                s1 += fmaxf(D[mb][nb][3] + b1v[nb][1], 0.f) * w2v[nb][1];
            }
            s0 += __shfl_xor_sync(0xffffffffu, s0, 1);
            s0 += __shfl_xor_sync(0xffffffffu, s0, 2);
            s1 += __shfl_xor_sync(0xffffffffu, s1, 1);
            s1 += __shfl_xor_sync(0xffffffffu, s1, 2);
            if (tq == 0) {
                int ebase = egrp * 32 + mb * 16 + tr;
                prt[ebase * 4 + cgrp]       = s0;
                prt[(ebase + 8) * 4 + cgrp] = s1;
            }
        }
        __syncthreads();
        if (tid < ETILE) {
            float4 p = ((const float4*)prt)[tid];
            float o = p.x + p.y + p.z + p.w + b2v;
            int eg = t * ETILE + tid;
            if (eg < E) out[eg] = o;
        }

        t = tn;
        buf ^= 1;
    }
}

extern "C" void kernel_launch(void* const* d_in, const int* in_sizes, int n_in,
                              void* d_out, int out_size)
{
    const float* zs  = (const float*)d_in[0];
    const float* zc  = (const float*)d_in[1];
    const int*   row = (const int*)d_in[2];
    const int*   col = (const int*)d_in[3];
    const float* W1  = (const float*)d_in[4];
    const float* b1  = (const float*)d_in[5];
    const float* W2  = (const float*)d_in[6];
    const float* b2  = (const float*)d_in[7];
    float* out = (float*)d_out;
    const int E = in_sizes[2];

    static bool attr_set = false;  // idempotent, not a work guard
    if (!attr_set) {
        cudaFuncSetAttribute(edge_decoder_mma,
                             cudaFuncAttributeMaxDynamicSharedMemorySize, SMEM_BYTES);
        attr_set = true;
    }

    int sms = 148;
    cudaDeviceGetAttribute(&sms, cudaDevAttrMultiProcessorCount, 0);

    // 1) convert embedding tables to fp16 scratch (deterministic, every call)
    cvt_tables<<<4 * sms, 256>>>(zs, zc);

    // 2) main fused gather + MMA kernel
    int numTiles = (E + ETILE - 1) / ETILE;
    int grid = sms < numTiles ? sms : numTiles;
    edge_decoder_mma<<<grid, NT, SMEM_BYTES>>>(row, col, W1, b1, W2, b2, out, E);
}

// round 9
// speedup vs baseline: 1.3021x; 1.3021x over previous
#include <cuda_runtime.h>
#include <cstdint>

#define NT     128
#define ETILE  64
#define HID    128
#define SROW   512                      // bytes per edge-row, 32 chunks of 16B, XOR-swizzled
#define ZBUF   (ETILE * SROW)           // 32768 B per buffer
#define OFF_PRT 0                       // 64 edges * 4 cgroups * 4B = 1024
#define OFF_Z   1024
#define SMEM_BYTES (OFF_Z + 2 * ZBUF)   // 66560 B -> 2 CTAs/SM (133 KB of 228 KB)

#define NS_U 6400000                    // student table in uint32 (fp16 pairs)
#define NC_U 1280000
__device__ uint32_t g_zh[NS_U + NC_U];  // fp16 tables scratch (31 MB)

// ---------------- helpers ----------------
__device__ __forceinline__ uint32_t smem_u32(const void* p) {
    uint32_t a;
    asm("{ .reg .u64 t; cvta.to.shared.u64 t, %1; cvt.u32.u64 %0, t; }" : "=r"(a) : "l"(p));
    return a;
}
__device__ __forceinline__ uint32_t hfpair(float lo, float hi) {
    uint32_t r;
    asm("cvt.rn.f16x2.f32 %0, %1, %2;" : "=r"(r) : "f"(hi), "f"(lo));
    return r;
}
__device__ __forceinline__ void ldmat4(uint32_t (&r)[4], uint32_t addr) {
    asm volatile("ldmatrix.sync.aligned.m8n8.x4.shared.b16 {%0,%1,%2,%3}, [%4];"
                 : "=r"(r[0]), "=r"(r[1]), "=r"(r[2]), "=r"(r[3]) : "r"(addr));
}
__device__ __forceinline__ void mma16816(float (&d)[4], const uint32_t (&a)[4],
                                         uint32_t b0, uint32_t b1) {
    asm volatile("mma.sync.aligned.m16n8k16.row.col.f32.f16.f16.f32 "
                 "{%0,%1,%2,%3}, {%4,%5,%6,%7}, {%8,%9}, {%0,%1,%2,%3};"
                 : "+f"(d[0]), "+f"(d[1]), "+f"(d[2]), "+f"(d[3])
                 : "r"(a[0]), "r"(a[1]), "r"(a[2]), "r"(a[3]), "r"(b0), "r"(b1));
}
#define CP_ASYNC16(dst, src) \
    asm volatile("cp.async.cg.shared.global [%0], [%1], 16;" :: "r"(dst), "l"(src) : "memory")
#define CP_COMMIT() asm volatile("cp.async.commit_group;" ::: "memory")
#define CP_WAIT(n)  asm volatile("cp.async.wait_group %0;" :: "n"(n) : "memory")

// ---------------- table convert: fp32 -> fp16 pairs (run each call) ----------------
__global__ void cvt_tables(const float* __restrict__ zs, const float* __restrict__ zc) {
    const int total = NS_U + NC_U;
    for (int i = blockIdx.x * blockDim.x + threadIdx.x; i < total;
         i += gridDim.x * blockDim.x) {
        const float* src = (i < NS_U) ? (zs + 2 * (size_t)i)
                                      : (zc + 2 * (size_t)(i - NS_U));
        g_zh[i] = hfpair(src[0], src[1]);
    }
}

// ---------------- gather via cp.async: 8 threads/edge, 4 passes of 16 edges ----------------
__device__ __forceinline__ void gather_async(const int* __restrict__ row,
                                             const int* __restrict__ col,
                                             int base, int E, int tid, uint32_t zdst) {
    const int q = tid & 7;
    #pragma unroll
    for (int pass = 0; pass < 4; pass++) {
        const int e_t = (tid >> 3) + pass * 16;
        const int eg  = base + e_t;
        const int ri  = (eg < E) ? row[eg] : 0;
        const int ci  = (eg < E) ? col[eg] : 0;
        const char* su = (const char*)(g_zh + (size_t)ri * 64);
        const char* cu = (const char*)(g_zh + NS_U + (size_t)ci * 64);
        const uint32_t rowp = zdst + (uint32_t)e_t * SROW;
        #pragma unroll
        for (int j = 0; j < 4; j++) {
            const int c  = 8 * j + q;                   // chunk 0..31
            const int cs = (c & 24) | ((c ^ e_t) & 7);  // XOR swizzle
            const char* src = (j < 2) ? (su + (c & 15) * 16) : (cu + (c & 15) * 16);
            CP_ASYNC16(rowp + cs * 16, src);
        }
    }
}

// ---------------- kernel ----------------
__global__ void __launch_bounds__(NT, 2)
edge_decoder_mma(const int* __restrict__ row, const int* __restrict__ col,
                 const float* __restrict__ W1, const float* __restrict__ b1,
                 const float* __restrict__ W2, const float* __restrict__ b2,
                 float* __restrict__ out, int E)
{
    extern __shared__ __align__(16) char sm[];
    float* prt = (float*)(sm + OFF_PRT);   // [64 edges][4 cgroups]
    char*  zsm = sm + OFF_Z;

    const int tid  = threadIdx.x;
    const int lane = tid & 31;
    const int wid  = tid >> 5;    // cgroup 0..3
    const int tq   = lane & 3;
    const int tr   = lane >> 2;
    const int wcol = wid * 32;

    // ---- B = W1 fragments, fp16, register-resident (128 regs) ----
    uint32_t B[4][16][2];
    #pragma unroll
    for (int nb = 0; nb < 4; nb++) {
        const int n = wcol + nb * 8 + tr;
        #pragma unroll
        for (int s = 0; s < 16; s++) {
            #pragma unroll
            for (int hh = 0; hh < 2; hh++) {
                const int k0 = s * 16 + tq * 2 + hh * 8;
                B[nb][s][hh] = hfpair(W1[(size_t)k0 * HID + n],
                                      W1[(size_t)(k0 + 1) * HID + n]);
            }
        }
    }

    // ---- epilogue constants ----
    float b1v[4][2], w2v[4][2];
    #pragma unroll
    for (int nb = 0; nb < 4; nb++)
        #pragma unroll
        for (int j = 0; j < 2; j++) {
            int c = wcol + nb * 8 + tq * 2 + j;
            b1v[nb][j] = b1[c];
            w2v[nb][j] = W2[c];
        }
    const float b2v = b2[0];

    const uint32_t zb0 = smem_u32(zsm);
    const int r0  = lane & 15;
    const int hh0 = lane >> 4;

    const int numTiles = (E + ETILE - 1) / ETILE;
    int t = blockIdx.x;
    int buf = 0;

    if (t < numTiles) {
        gather_async(row, col, t * ETILE, E, tid, zb0);
        CP_COMMIT();
    }

    while (t < numTiles) {
        const int tn = t + gridDim.x;

        // issue next tile's gather into other buffer, then wait for current
        if (tn < numTiles) {
            gather_async(row, col, tn * ETILE, E, tid, zb0 + (uint32_t)(buf ^ 1) * ZBUF);
            CP_COMMIT();
            CP_WAIT(1);
        } else {
            CP_WAIT(0);
        }
        __syncthreads();   // buf visible; prt from prev tile consumed

        // ---- MMA mainloop: mb=4 x nb=4, 16 k-steps ----
        float D[4][4][4];
        #pragma unroll
        for (int mb = 0; mb < 4; mb++)
            #pragma unroll
            for (int nb = 0; nb < 4; nb++)
                #pragma unroll
                for (int i = 0; i < 4; i++) D[mb][nb][i] = 0.f;

        const uint32_t zb = zb0 + (uint32_t)buf * ZBUF;
        #pragma unroll
        for (int s = 0; s < 16; s++) {
            uint32_t A[4][4];
            #pragma unroll
            for (int mb = 0; mb < 4; mb++) {
                const int r  = mb * 16 + r0;
                const int c  = 2 * s + hh0;
                const int cs = (c & 24) | ((c ^ r) & 7);
                ldmat4(A[mb], zb + (uint32_t)(r * SROW + cs * 16));
            }
            #pragma unroll
            for (int mb = 0; mb < 4; mb++)
                #pragma unroll
                for (int nb = 0; nb < 4; nb++)
                    mma16816(D[mb][nb], A[mb], B[nb][s][0], B[nb][s][1]);
        }

        // ---- epilogue: bias + ReLU + W2, quad-reduce, stash partials ----
        #pragma unroll
        for (int mb = 0; mb < 4; mb++) {
            float s0 = 0.f, s1 = 0.f;
            #pragma unroll
            for (int nb = 0; nb < 4; nb++) {
                s0 += fmaxf(D[mb][nb][0] + b1v[nb][0], 0.f) * w2v[nb][0];
                s0 += fmaxf(D[mb][nb][1] + b1v[nb][1], 0.f) * w2v[nb][1];
                s1 += fmaxf(D[mb][nb][2] + b1v[nb][0], 0.f) * w2v[nb][0];
                s1 += fmaxf(D[mb][nb][3] + b1v[nb][1], 0.f) * w2v[nb][1];
            }
            s0 += __shfl_xor_sync(0xffffffffu, s0, 1);
            s0 += __shfl_xor_sync(0xffffffffu, s0, 2);
            s1 += __shfl_xor_sync(0xffffffffu, s1, 1);
            s1 += __shfl_xor_sync(0xffffffffu, s1, 2);
            if (tq == 0) {
                int ebase = mb * 16 + tr;
                prt[ebase * 4 + wid]       = s0;
                prt[(ebase + 8) * 4 + wid] = s1;
            }
        }
        __syncthreads();
        if (tid < ETILE) {
            float4 p = ((const float4*)prt)[tid];
            float o = p.x + p.y + p.z + p.w + b2v;
            int eg = t * ETILE + tid;
            if (eg < E) out[eg] = o;
        }

        t = tn;
        buf ^= 1;
    }
}

extern "C" void kernel_launch(void* const* d_in, const int* in_sizes, int n_in,
                              void* d_out, int out_size)
{
    const float* zs  = (const float*)d_in[0];
    const float* zc  = (const float*)d_in[1];
    const int*   row = (const int*)d_in[2];
    const int*   col = (const int*)d_in[3];
    const float* W1  = (const float*)d_in[4];
    const float* b1  = (const float*)d_in[5];
    const float* W2  = (const float*)d_in[6];
    const float* b2  = (const float*)d_in[7];
    float* out = (float*)d_out;
    const int E = in_sizes[2];

    static bool attr_set = false;  // idempotent, not a work guard
    if (!attr_set) {
        cudaFuncSetAttribute(edge_decoder_mma,
                             cudaFuncAttributeMaxDynamicSharedMemorySize, SMEM_BYTES);
        attr_set = true;
    }

    int sms = 148;
    cudaDeviceGetAttribute(&sms, cudaDevAttrMultiProcessorCount, 0);

    // 1) convert embedding tables to fp16 scratch (deterministic, every call)
    cvt_tables<<<4 * sms, 256>>>(zs, zc);

    // 2) main fused gather + MMA kernel: 2 CTAs per SM, phase-decoupled
    int numTiles = (E + ETILE - 1) / ETILE;
    int grid = 2 * sms;
    if (grid > numTiles) grid = numTiles;
    edge_decoder_mma<<<grid, NT, SMEM_BYTES>>>(row, col, W1, b1, W2, b2, out, E);
}